// round 1
// baseline (speedup 1.0000x reference)
#include <cuda_runtime.h>
#include <cstddef>

// Problem constants (fixed by setup_inputs)
#define Bsz  8
#define Nn   4096
#define Ee   16384
#define Pp   64
#define Dd   256
#define Hh   512
#define MSGd 256
#define UPDd 254
#define STEPS 3

// ---------------- scratch (allocation-free: __device__ globals) ----------------
__device__ float g_ns  [(size_t)Bsz*Nn*Dd];    // working node states (33.5 MB)
__device__ float g_he  [(size_t)Bsz*Ee*Hh];    // edge hidden        (268 MB)
__device__ float g_msgs[(size_t)Bsz*Ee*MSGd];  // messages           (134 MB)
__device__ float g_inc [(size_t)Bsz*Nn*MSGd];  // incoming           (33.5 MB)
__device__ float g_h2  [(size_t)Bsz*Nn*Hh];    // node hidden        (67 MB)
__device__ float g_w2p [Hh*256];               // W_n2 padded 254->256
__device__ float g_b2p [256];                  // b_n2 padded

// ---------------- small utility kernels ----------------
__global__ void copy4_k(float4* __restrict__ dst, const float4* __restrict__ src, int n4) {
    int i = blockIdx.x * blockDim.x + threadIdx.x;
    if (i < n4) dst[i] = src[i];
}
__global__ void zero4_k(float4* __restrict__ dst, int n4) {
    int i = blockIdx.x * blockDim.x + threadIdx.x;
    if (i < n4) dst[i] = make_float4(0.f, 0.f, 0.f, 0.f);
}
__global__ void pad_w_k(const float* __restrict__ w, const float* __restrict__ b) {
    int i = blockIdx.x * blockDim.x + threadIdx.x;   // over Hh*256
    int r = i >> 8, c = i & 255;
    g_w2p[i] = (c < UPDd) ? w[r * UPDd + c] : 0.f;
    if (i < 256) g_b2p[i] = (i < UPDd) ? b[i] : 0.f;
}

// ---------------- scatter-add: incoming[b, sink[e], :] += msgs[b, e, :] ----------------
__global__ void scatter_k(const float* __restrict__ msgs, const int* __restrict__ sinks,
                          float* __restrict__ inc) {
    int be = blockIdx.x;                 // b*E + e
    int b = be >> 14;                    // / E (E = 16384)
    int e = be & (Ee - 1);
    int s = sinks[e];
    float v = msgs[(size_t)be * MSGd + threadIdx.x];
    atomicAdd(&inc[((size_t)b * Nn + s) * MSGd + threadIdx.x], v);
}

// ---------------- tiled SGEMM: 128x128x16, 8x8 per thread, 256 threads ----------------
// MODE 0: plain A (M x K row-major)
// MODE 1: gathered edge concat: row m=(b,e); k<D -> ns[b,src[e],k], else ns[b,snk[e],k-D]
// MODE 2: concat: k<MSG -> A0[m*MSG+k] (incoming), else A1[m*D+(k-MSG)] (ns)
// Epilogue: +bias, optional relu; ADDNS: C(=ns)[m*D + 2 + n] += v for n<UPD
constexpr int BM = 128, BN = 128, BK = 16, TM = 8, TN = 8;

template <int MODE, bool RELU, bool ADDNS>
__global__ void __launch_bounds__(256)
gemm_k(const float* __restrict__ A0, const float* __restrict__ A1,
       const int* __restrict__ idx0, const int* __restrict__ idx1,
       const float* __restrict__ Bm, const float* __restrict__ bias,
       float* __restrict__ C, int K, int ldb, int ldc)
{
    __shared__ float As[BK][BM];
    __shared__ float Bs[BK][BN];
    __shared__ long long rowOff0[BM];
    __shared__ long long rowOff1[BM];

    const int tid = threadIdx.x;
    const int m0 = blockIdx.y * BM;
    const int n0 = blockIdx.x * BN;

    if (MODE == 1) {
        if (tid < BM) {
            int m = m0 + tid;
            int b = m >> 14;              // / E
            int e = m & (Ee - 1);
            rowOff0[tid] = ((long long)b * Nn + idx0[e]) * Dd;
            rowOff1[tid] = ((long long)b * Nn + idx1[e]) * Dd;
        }
        __syncthreads();
    }

    float acc[TM][TN];
#pragma unroll
    for (int i = 0; i < TM; i++)
#pragma unroll
        for (int j = 0; j < TN; j++) acc[i][j] = 0.f;

    const int ty = tid >> 4;             // 0..15
    const int tx = tid & 15;             // 0..15
    const int a_row = tid >> 2;          // 0..63
    const int a_k   = (tid & 3) * 4;     // 0,4,8,12
    const int b_k   = tid >> 5;          // 0..7
    const int b_n   = (tid & 31) * 4;    // 0..124

    for (int kt = 0; kt < K; kt += BK) {
        // ---- load A tile (128 x 16), store transposed As[k][m] ----
#pragma unroll
        for (int r = 0; r < 2; r++) {
            int row = a_row + r * 64;
            float4 v;
            if (MODE == 0) {
                v = *reinterpret_cast<const float4*>(A0 + (size_t)(m0 + row) * K + kt + a_k);
            } else if (MODE == 1) {
                long long base = (kt < Dd) ? rowOff0[row] : rowOff1[row];
                int ko = (kt < Dd) ? (kt + a_k) : (kt - Dd + a_k);
                v = *reinterpret_cast<const float4*>(A0 + base + ko);
            } else {
                if (kt < MSGd)
                    v = *reinterpret_cast<const float4*>(A0 + (size_t)(m0 + row) * MSGd + kt + a_k);
                else
                    v = *reinterpret_cast<const float4*>(A1 + (size_t)(m0 + row) * Dd + (kt - MSGd) + a_k);
            }
            As[a_k + 0][row] = v.x;
            As[a_k + 1][row] = v.y;
            As[a_k + 2][row] = v.z;
            As[a_k + 3][row] = v.w;
        }
        // ---- load B tile (16 x 128) ----
#pragma unroll
        for (int r = 0; r < 2; r++) {
            int kk = b_k + r * 8;
            float4 v = *reinterpret_cast<const float4*>(Bm + (size_t)(kt + kk) * ldb + n0 + b_n);
            *reinterpret_cast<float4*>(&Bs[kk][b_n]) = v;
        }
        __syncthreads();

#pragma unroll
        for (int kk = 0; kk < BK; kk++) {
            float ar[TM], br[TN];
            *reinterpret_cast<float4*>(&ar[0]) = *reinterpret_cast<float4*>(&As[kk][ty * TM]);
            *reinterpret_cast<float4*>(&ar[4]) = *reinterpret_cast<float4*>(&As[kk][ty * TM + 4]);
            *reinterpret_cast<float4*>(&br[0]) = *reinterpret_cast<float4*>(&Bs[kk][tx * TN]);
            *reinterpret_cast<float4*>(&br[4]) = *reinterpret_cast<float4*>(&Bs[kk][tx * TN + 4]);
#pragma unroll
            for (int i = 0; i < TM; i++)
#pragma unroll
                for (int j = 0; j < TN; j++) acc[i][j] += ar[i] * br[j];
        }
        __syncthreads();
    }

    // ---- epilogue ----
#pragma unroll
    for (int i = 0; i < TM; i++) {
        int m = m0 + ty * TM + i;
#pragma unroll
        for (int j = 0; j < TN; j++) {
            int n = n0 + tx * TN + j;
            float v = acc[i][j] + bias[n];
            if (RELU) v = fmaxf(v, 0.f);
            if (ADDNS) {
                if (n < UPDd) C[(size_t)m * Dd + (Dd - UPDd) + n] += v;
            } else {
                C[(size_t)m * ldc + n] = v;
            }
        }
    }
}

// ---------------- extraction: out[b,p,d] = sum_n attn[b,p,n] * ns[b,n,d] ----------------
__global__ void __launch_bounds__(256) extract_k(const float* __restrict__ attn,
                                                 const float* __restrict__ nsg,
                                                 float* __restrict__ out) {
    __shared__ float sa[512];
    int bp = blockIdx.x;                       // b*P + p
    int b = bp >> 6;                           // / P (P = 64)
    const float* arow = attn + (size_t)bp * Nn;
    const float* nsb  = nsg + (size_t)b * Nn * Dd;
    int d = threadIdx.x;
    float acc = 0.f;
    for (int n0 = 0; n0 < Nn; n0 += 512) {
        sa[d]       = arow[n0 + d];
        sa[d + 256] = arow[n0 + d + 256];
        __syncthreads();
#pragma unroll 8
        for (int n = 0; n < 512; n++)
            acc += sa[n] * nsb[(size_t)(n0 + n) * Dd + d];
        __syncthreads();
    }
    out[(size_t)bp * Dd + d] = acc;
}

// ---------------- launch ----------------
extern "C" void kernel_launch(void* const* d_in, const int* in_sizes, int n_in,
                              void* d_out, int out_size) {
    const float* nodes = (const float*)d_in[0];
    const float* attn  = (const float*)d_in[1];
    const float* W_e1  = (const float*)d_in[2];
    const float* b_e1  = (const float*)d_in[3];
    const float* W_e2  = (const float*)d_in[4];
    const float* b_e2  = (const float*)d_in[5];
    const float* W_n1  = (const float*)d_in[6];
    const float* b_n1  = (const float*)d_in[7];
    const float* W_n2  = (const float*)d_in[8];
    const float* b_n2  = (const float*)d_in[9];
    const int*   srcI  = (const int*)d_in[10];
    const int*   snkI  = (const int*)d_in[11];
    // d_in[12] = msg_steps, fixed at 3 in the dataset (device scalar; unreadable under capture)

    float *p_ns, *p_he, *p_msgs, *p_inc, *p_h2, *p_w2p, *p_b2p;
    cudaGetSymbolAddress((void**)&p_ns,   g_ns);
    cudaGetSymbolAddress((void**)&p_he,   g_he);
    cudaGetSymbolAddress((void**)&p_msgs, g_msgs);
    cudaGetSymbolAddress((void**)&p_inc,  g_inc);
    cudaGetSymbolAddress((void**)&p_h2,   g_h2);
    cudaGetSymbolAddress((void**)&p_w2p,  g_w2p);
    cudaGetSymbolAddress((void**)&p_b2p,  g_b2p);

    const int nsElems  = Bsz * Nn * Dd;       // 8,388,608
    const int incElems = Bsz * Nn * MSGd;     // 8,388,608

    // fresh working copy of node states + padded node-MLP-2 weights
    copy4_k<<<nsElems / 4 / 256, 256>>>((float4*)p_ns, (const float4*)nodes, nsElems / 4);
    pad_w_k<<<(Hh * 256) / 256, 256>>>(W_n2, b_n2);

    const int ME = Bsz * Ee;   // 131072 edge rows
    const int MN = Bsz * Nn;   // 32768 node rows

    for (int s = 0; s < STEPS; s++) {
        // edge MLP layer 1 (gather concat[src,snk] @ W_e1, relu)
        gemm_k<1, true, false><<<dim3(Hh / BN, ME / BM), 256>>>(
            p_ns, nullptr, srcI, snkI, W_e1, b_e1, p_he, 2 * Dd, Hh, Hh);
        // edge MLP layer 2 (msgs = he @ W_e2 + b)
        gemm_k<0, false, false><<<dim3(MSGd / BN, ME / BM), 256>>>(
            p_he, nullptr, nullptr, nullptr, W_e2, b_e2, p_msgs, Hh, MSGd, MSGd);
        // zero + scatter-add incoming
        zero4_k<<<incElems / 4 / 256, 256>>>((float4*)p_inc, incElems / 4);
        scatter_k<<<ME, MSGd>>>(p_msgs, snkI, p_inc);
        // node MLP layer 1 (concat[incoming, ns] @ W_n1, relu)
        gemm_k<2, true, false><<<dim3(Hh / BN, MN / BM), 256>>>(
            p_inc, p_ns, nullptr, nullptr, W_n1, b_n1, p_h2, MSGd + Dd, Hh, Hh);
        // node MLP layer 2 + residual add into ns[:, :, 2:256]
        gemm_k<0, false, true><<<dim3(256 / BN, MN / BM), 256>>>(
            p_h2, nullptr, nullptr, nullptr, p_w2p, p_b2p, p_ns, Hh, 256, Dd);
    }

    // extraction: (B,P,N) x (B,N,D) -> (B,P,D)
    extract_k<<<Bsz * Pp, 256>>>(attn, p_ns, (float*)d_out);
}

// round 2
// speedup vs baseline: 1.0816x; 1.0816x over previous
#include <cuda_runtime.h>
#include <cstddef>

// Problem constants (fixed by setup_inputs)
#define Bsz  8
#define Nn   4096
#define Ee   16384
#define Pp   64
#define Dd   256
#define Hh   512
#define MSGd 256
#define UPDd 254
#define STEPS 3

// ---------------- scratch (allocation-free: __device__ globals) ----------------
__device__ float g_ns  [(size_t)Bsz*Nn*Dd];    // working node states (33.5 MB)
__device__ float g_he  [(size_t)Bsz*Ee*Hh];    // edge hidden        (268 MB)
__device__ float g_msgs[(size_t)Bsz*Ee*MSGd];  // messages           (134 MB)
__device__ float g_inc [(size_t)Bsz*Nn*MSGd];  // incoming           (33.5 MB)
__device__ float g_h2  [(size_t)Bsz*Nn*Hh];    // node hidden        (67 MB)
__device__ float g_w2p [Hh*256];               // W_n2 padded 254->256
__device__ float g_b2p [256];                  // b_n2 padded

// ---------------- packed fp32x2 helpers (sm_103a FFMA2 path) ----------------
__device__ __forceinline__ unsigned long long pack2(float x, float y) {
    unsigned long long r;
    asm("mov.b64 %0, {%1, %2};" : "=l"(r) : "f"(x), "f"(y));
    return r;
}
__device__ __forceinline__ void unpack2(unsigned long long p, float& x, float& y) {
    asm("mov.b64 {%0, %1}, %2;" : "=f"(x), "=f"(y) : "l"(p));
}
__device__ __forceinline__ unsigned long long ffma2(unsigned long long a,
                                                    unsigned long long b,
                                                    unsigned long long c) {
    unsigned long long d;
    asm("fma.rn.f32x2 %0, %1, %2, %3;" : "=l"(d) : "l"(a), "l"(b), "l"(c));
    return d;
}

// ---------------- small utility kernels ----------------
__global__ void copy4_k(float4* __restrict__ dst, const float4* __restrict__ src, int n4) {
    int i = blockIdx.x * blockDim.x + threadIdx.x;
    if (i < n4) dst[i] = src[i];
}
__global__ void zero4_k(float4* __restrict__ dst, int n4) {
    int i = blockIdx.x * blockDim.x + threadIdx.x;
    if (i < n4) dst[i] = make_float4(0.f, 0.f, 0.f, 0.f);
}
__global__ void pad_w_k(const float* __restrict__ w, const float* __restrict__ b) {
    int i = blockIdx.x * blockDim.x + threadIdx.x;   // over Hh*256
    int r = i >> 8, c = i & 255;
    g_w2p[i] = (c < UPDd) ? w[r * UPDd + c] : 0.f;
    if (i < 256) g_b2p[i] = (i < UPDd) ? b[i] : 0.f;
}

// ---------------- scatter-add: incoming[b, sink[e], :] += msgs[b, e, :] ----------------
__global__ void scatter_k(const float* __restrict__ msgs, const int* __restrict__ sinks,
                          float* __restrict__ inc) {
    int be = blockIdx.x;                 // b*E + e
    int b = be >> 14;                    // / E (E = 16384)
    int e = be & (Ee - 1);
    int s = sinks[e];
    float v = msgs[(size_t)be * MSGd + threadIdx.x];
    atomicAdd(&inc[((size_t)b * Nn + s) * MSGd + threadIdx.x], v);
}

// ---------------- tiled SGEMM: 128x128x16, 8x8 per thread, 256 threads ----------------
// Double-buffered smem, packed f32x2 inner product.
// MODE 0: plain A (M x K row-major)
// MODE 1: gathered edge concat: row m=(b,e); k<D -> ns[b,src[e],k], else ns[b,snk[e],k-D]
// MODE 2: concat: k<MSG -> A0[m*MSG+k] (incoming), else A1[m*D+(k-MSG)] (ns)
// Epilogue: +bias, optional relu; ADDNS: C(=ns)[m*D + 2 + n] += v for n<UPD
constexpr int BM = 128, BN = 128, BK = 16, TM = 8, TN = 8;
constexpr int AP = BM + 4;   // padded A row stride (132 floats; 528B, 16B-aligned)

template <int MODE, bool RELU, bool ADDNS>
__global__ void __launch_bounds__(256)
gemm_k(const float* __restrict__ A0, const float* __restrict__ A1,
       const int* __restrict__ idx0, const int* __restrict__ idx1,
       const float* __restrict__ Bm, const float* __restrict__ bias,
       float* __restrict__ C, int K, int ldb, int ldc)
{
    __shared__ __align__(16) float As[2][BK][AP];
    __shared__ __align__(16) float Bs[2][BK][BN];
    __shared__ long long rowOff0[BM];
    __shared__ long long rowOff1[BM];

    const int tid = threadIdx.x;
    const int m0 = blockIdx.y * BM;
    const int n0 = blockIdx.x * BN;

    if (MODE == 1) {
        if (tid < BM) {
            int m = m0 + tid;
            int b = m >> 14;              // / E
            int e = m & (Ee - 1);
            rowOff0[tid] = ((long long)b * Nn + idx0[e]) * Dd;
            rowOff1[tid] = ((long long)b * Nn + idx1[e]) * Dd;
        }
        __syncthreads();
    }

    unsigned long long acc2[TM][TN / 2];
#pragma unroll
    for (int i = 0; i < TM; i++)
#pragma unroll
        for (int j = 0; j < TN / 2; j++) acc2[i][j] = 0ull;

    const int ty = tid >> 4;             // 0..15
    const int tx = tid & 15;             // 0..15
    const int a_row = tid >> 2;          // 0..63
    const int a_k   = (tid & 3) * 4;     // 0,4,8,12
    const int b_k   = tid >> 5;          // 0..7
    const int b_n   = (tid & 31) * 4;    // 0..124

    float4 aReg[2], bReg[2];

    // ---- fetch helpers (register staging) ----
    auto fetchA = [&](int kt) {
#pragma unroll
        for (int r = 0; r < 2; r++) {
            int row = a_row + r * 64;
            if (MODE == 0) {
                aReg[r] = *reinterpret_cast<const float4*>(A0 + (size_t)(m0 + row) * K + kt + a_k);
            } else if (MODE == 1) {
                long long base = (kt < Dd) ? rowOff0[row] : rowOff1[row];
                int ko = (kt < Dd) ? (kt + a_k) : (kt - Dd + a_k);
                aReg[r] = *reinterpret_cast<const float4*>(A0 + base + ko);
            } else {
                if (kt < MSGd)
                    aReg[r] = *reinterpret_cast<const float4*>(A0 + (size_t)(m0 + row) * MSGd + kt + a_k);
                else
                    aReg[r] = *reinterpret_cast<const float4*>(A1 + (size_t)(m0 + row) * Dd + (kt - MSGd) + a_k);
            }
        }
#pragma unroll
        for (int r = 0; r < 2; r++) {
            int kk = b_k + r * 8;
            bReg[r] = *reinterpret_cast<const float4*>(Bm + (size_t)(kt + kk) * ldb + n0 + b_n);
        }
    };
    auto stash = [&](int buf) {
#pragma unroll
        for (int r = 0; r < 2; r++) {
            int row = a_row + r * 64;
            As[buf][a_k + 0][row] = aReg[r].x;
            As[buf][a_k + 1][row] = aReg[r].y;
            As[buf][a_k + 2][row] = aReg[r].z;
            As[buf][a_k + 3][row] = aReg[r].w;
        }
#pragma unroll
        for (int r = 0; r < 2; r++) {
            int kk = b_k + r * 8;
            *reinterpret_cast<float4*>(&Bs[buf][kk][b_n]) = bReg[r];
        }
    };
    auto compute = [&](int buf) {
#pragma unroll
        for (int kk = 0; kk < BK; kk++) {
            float ar[TM];
            *reinterpret_cast<float4*>(&ar[0]) = *reinterpret_cast<const float4*>(&As[buf][kk][ty * TM]);
            *reinterpret_cast<float4*>(&ar[4]) = *reinterpret_cast<const float4*>(&As[buf][kk][ty * TM + 4]);
            unsigned long long br2[TN / 2];
            const unsigned long long* bp =
                reinterpret_cast<const unsigned long long*>(&Bs[buf][kk][tx * TN]);
#pragma unroll
            for (int j = 0; j < TN / 2; j++) br2[j] = bp[j];
#pragma unroll
            for (int i = 0; i < TM; i++) {
                unsigned long long a2 = pack2(ar[i], ar[i]);
#pragma unroll
                for (int j = 0; j < TN / 2; j++)
                    acc2[i][j] = ffma2(a2, br2[j], acc2[i][j]);
            }
        }
    };

    // ---- software pipeline: prefetch tile kt+BK while computing tile kt ----
    fetchA(0);
    stash(0);
    __syncthreads();
    int buf = 0;
    for (int kt = BK; kt < K; kt += BK) {
        fetchA(kt);
        compute(buf);
        stash(buf ^ 1);
        __syncthreads();
        buf ^= 1;
    }
    compute(buf);

    // ---- epilogue ----
#pragma unroll
    for (int i = 0; i < TM; i++) {
        int m = m0 + ty * TM + i;
#pragma unroll
        for (int j = 0; j < TN / 2; j++) {
            float v0, v1;
            unpack2(acc2[i][j], v0, v1);
            int n = n0 + tx * TN + 2 * j;
            v0 += bias[n];
            v1 += bias[n + 1];
            if (RELU) { v0 = fmaxf(v0, 0.f); v1 = fmaxf(v1, 0.f); }
            if (ADDNS) {
                if (n < UPDd)     C[(size_t)m * Dd + (Dd - UPDd) + n]     += v0;
                if (n + 1 < UPDd) C[(size_t)m * Dd + (Dd - UPDd) + n + 1] += v1;
            } else {
                C[(size_t)m * ldc + n]     = v0;
                C[(size_t)m * ldc + n + 1] = v1;
            }
        }
    }
}

// ---------------- extraction: out[b,p,d] = sum_n attn[b,p,n] * ns[b,n,d] ----------------
__global__ void __launch_bounds__(256) extract_k(const float* __restrict__ attn,
                                                 const float* __restrict__ nsg,
                                                 float* __restrict__ out) {
    __shared__ float sa[512];
    int bp = blockIdx.x;                       // b*P + p
    int b = bp >> 6;                           // / P (P = 64)
    const float* arow = attn + (size_t)bp * Nn;
    const float* nsb  = nsg + (size_t)b * Nn * Dd;
    int d = threadIdx.x;
    float acc = 0.f;
    for (int n0 = 0; n0 < Nn; n0 += 512) {
        sa[d]       = arow[n0 + d];
        sa[d + 256] = arow[n0 + d + 256];
        __syncthreads();
#pragma unroll 8
        for (int n = 0; n < 512; n++)
            acc += sa[n] * nsb[(size_t)(n0 + n) * Dd + d];
        __syncthreads();
    }
    out[(size_t)bp * Dd + d] = acc;
}

// ---------------- launch ----------------
extern "C" void kernel_launch(void* const* d_in, const int* in_sizes, int n_in,
                              void* d_out, int out_size) {
    const float* nodes = (const float*)d_in[0];
    const float* attn  = (const float*)d_in[1];
    const float* W_e1  = (const float*)d_in[2];
    const float* b_e1  = (const float*)d_in[3];
    const float* W_e2  = (const float*)d_in[4];
    const float* b_e2  = (const float*)d_in[5];
    const float* W_n1  = (const float*)d_in[6];
    const float* b_n1  = (const float*)d_in[7];
    const float* W_n2  = (const float*)d_in[8];
    const float* b_n2  = (const float*)d_in[9];
    const int*   srcI  = (const int*)d_in[10];
    const int*   snkI  = (const int*)d_in[11];
    // d_in[12] = msg_steps, fixed at 3 in the dataset (device scalar; unreadable under capture)

    float *p_ns, *p_he, *p_msgs, *p_inc, *p_h2, *p_w2p, *p_b2p;
    cudaGetSymbolAddress((void**)&p_ns,   g_ns);
    cudaGetSymbolAddress((void**)&p_he,   g_he);
    cudaGetSymbolAddress((void**)&p_msgs, g_msgs);
    cudaGetSymbolAddress((void**)&p_inc,  g_inc);
    cudaGetSymbolAddress((void**)&p_h2,   g_h2);
    cudaGetSymbolAddress((void**)&p_w2p,  g_w2p);
    cudaGetSymbolAddress((void**)&p_b2p,  g_b2p);

    const int nsElems  = Bsz * Nn * Dd;       // 8,388,608
    const int incElems = Bsz * Nn * MSGd;     // 8,388,608

    // fresh working copy of node states + padded node-MLP-2 weights
    copy4_k<<<nsElems / 4 / 256, 256>>>((float4*)p_ns, (const float4*)nodes, nsElems / 4);
    pad_w_k<<<(Hh * 256) / 256, 256>>>(W_n2, b_n2);

    const int ME = Bsz * Ee;   // 131072 edge rows
    const int MN = Bsz * Nn;   // 32768 node rows

    for (int s = 0; s < STEPS; s++) {
        // edge MLP layer 1 (gather concat[src,snk] @ W_e1, relu)
        gemm_k<1, true, false><<<dim3(Hh / BN, ME / BM), 256>>>(
            p_ns, nullptr, srcI, snkI, W_e1, b_e1, p_he, 2 * Dd, Hh, Hh);
        // edge MLP layer 2 (msgs = he @ W_e2 + b)
        gemm_k<0, false, false><<<dim3(MSGd / BN, ME / BM), 256>>>(
            p_he, nullptr, nullptr, nullptr, W_e2, b_e2, p_msgs, Hh, MSGd, MSGd);
        // zero + scatter-add incoming
        zero4_k<<<incElems / 4 / 256, 256>>>((float4*)p_inc, incElems / 4);
        scatter_k<<<ME, MSGd>>>(p_msgs, snkI, p_inc);
        // node MLP layer 1 (concat[incoming, ns] @ W_n1, relu)
        gemm_k<2, true, false><<<dim3(Hh / BN, MN / BM), 256>>>(
            p_inc, p_ns, nullptr, nullptr, W_n1, b_n1, p_h2, MSGd + Dd, Hh, Hh);
        // node MLP layer 2 + residual add into ns[:, :, 2:256]
        gemm_k<0, false, true><<<dim3(256 / BN, MN / BM), 256>>>(
            p_h2, nullptr, nullptr, nullptr, p_w2p, p_b2p, p_ns, Hh, 256, Dd);
    }

    // extraction: (B,P,N) x (B,N,D) -> (B,P,D)
    extract_k<<<Bsz * Pp, 256>>>(attn, p_ns, (float*)d_out);
}

// round 5
// speedup vs baseline: 1.7607x; 1.6279x over previous
#include <cuda_runtime.h>
#include <cuda_bf16.h>
#include <cstddef>
#include <cstdint>

// Problem constants (fixed by setup_inputs)
#define Bsz  8
#define Nn   4096
#define Ee   16384
#define Pp   64
#define Dd   256
#define Hh   512
#define MSGd 256
#define UPDd 254
#define STEPS 3

// ---------------- scratch (allocation-free: __device__ globals) ----------------
__device__ float g_ns  [(size_t)Bsz*Nn*Dd];    // working node states
__device__ float g_he  [(size_t)Bsz*Ee*Hh];    // edge hidden
__device__ float g_msgs[(size_t)Bsz*Ee*MSGd];  // messages
__device__ float g_inc [(size_t)Bsz*Nn*MSGd];  // incoming
__device__ float g_h2  [(size_t)Bsz*Nn*Hh];    // node hidden
__device__ float g_b2p [256];                  // b_n2 padded
// transposed + hi/lo-split weights (bf16), layout Wt[N][K] K-major
__device__ __nv_bfloat16 g_wte1h[512*512], g_wte1l[512*512];
__device__ __nv_bfloat16 g_wte2h[256*512], g_wte2l[256*512];
__device__ __nv_bfloat16 g_wtn1h[512*512], g_wtn1l[512*512];
__device__ __nv_bfloat16 g_wtn2h[256*512], g_wtn2l[256*512];

// ---------------- PTX helpers (family-portable only: ldmatrix + mma.sync) ----------------
__device__ __forceinline__ uint32_t smem_u32(const void* p) {
    uint32_t a;
    asm("{ .reg .u64 t; cvta.to.shared.u64 t, %1; cvt.u32.u64 %0, t; }" : "=r"(a) : "l"(p));
    return a;
}
__device__ __forceinline__ void ldsm4(uint32_t* r, uint32_t addr) {
    asm volatile("ldmatrix.sync.aligned.m8n8.x4.shared.b16 {%0,%1,%2,%3}, [%4];"
                 : "=r"(r[0]), "=r"(r[1]), "=r"(r[2]), "=r"(r[3]) : "r"(addr));
}
__device__ __forceinline__ void mma16816(float* c, const uint32_t* a, uint32_t b0, uint32_t b1) {
    asm volatile(
        "mma.sync.aligned.m16n8k16.row.col.f32.bf16.bf16.f32 "
        "{%0,%1,%2,%3}, {%4,%5,%6,%7}, {%8,%9}, {%0,%1,%2,%3};"
        : "+f"(c[0]), "+f"(c[1]), "+f"(c[2]), "+f"(c[3])
        : "r"(a[0]), "r"(a[1]), "r"(a[2]), "r"(a[3]), "r"(b0), "r"(b1));
}
__device__ __forceinline__ uint32_t sw128(uint32_t off) { return off ^ ((off >> 3) & 0x70); }

// ---------------- small utility kernels ----------------
__global__ void copy4_k(float4* __restrict__ dst, const float4* __restrict__ src, int n4) {
    int i = blockIdx.x * blockDim.x + threadIdx.x;
    if (i < n4) dst[i] = src[i];
}
__global__ void zero4_k(float4* __restrict__ dst, int n4) {
    int i = blockIdx.x * blockDim.x + threadIdx.x;
    if (i < n4) dst[i] = make_float4(0.f, 0.f, 0.f, 0.f);
}
// transpose + hi/lo split: out[n][k] = split(W[k][n]); n >= srcN -> 0 (padding)
__global__ void tsplit_k(const float* __restrict__ W, __nv_bfloat16* __restrict__ Hi,
                         __nv_bfloat16* __restrict__ Lo, int K, int N, int srcN) {
    int i = blockIdx.x * 256 + threadIdx.x;
    if (i >= N * K) return;
    int n = i / K, k = i - n * K;
    float v = (n < srcN) ? W[(size_t)k * srcN + n] : 0.f;
    __nv_bfloat16 h = __float2bfloat16(v);
    Hi[i] = h;
    Lo[i] = __float2bfloat16(v - __bfloat162float(h));
}
__global__ void padb_k(const float* __restrict__ b) {
    int i = threadIdx.x;
    g_b2p[i] = (i < UPDd) ? b[i] : 0.f;
}

// ---------------- scatter-add ----------------
__global__ void scatter_k(const float* __restrict__ msgs, const int* __restrict__ sinks,
                          float* __restrict__ inc) {
    int be = blockIdx.x;
    int b = be >> 14;
    int e = be & (Ee - 1);
    int s = sinks[e];
    float v = msgs[(size_t)be * MSGd + threadIdx.x];
    atomicAdd(&inc[((size_t)b * Nn + s) * MSGd + threadIdx.x], v);
}

// ---------------- HMMA GEMM: 128x128 tile, BK=64, bf16 3-pass hi/lo emulation ----------------
// MODE 0: A0[m][k] row-major, row stride = K
// MODE 1: gather concat: k<256 -> ns[rowOff0[m]+k], else ns[rowOff1[m]+k-256]
// MODE 2: concat: k<256 -> A0[m*256+k] (incoming), else A1[m*256+(k-256)] (ns)
// Weights: WtHi/WtLo bf16 [N][K] K-major
// Dyn smem per stage (64 KB): AHI 16K | ALO 16K | BHI 16K | BLO 16K. 2 stages.
#define STAGE_SZ 65536
#define SMEM_BYTES (2 * STAGE_SZ)

template <int MODE, bool RELU, bool ADDNS>
__global__ void __launch_bounds__(256, 1)
gemm_mma(const float* __restrict__ A0, const float* __restrict__ A1,
         const int* __restrict__ idx0, const int* __restrict__ idx1,
         const __nv_bfloat16* __restrict__ WtHi, const __nv_bfloat16* __restrict__ WtLo,
         const float* __restrict__ bias, float* __restrict__ C,
         int K, int ldc)
{
    extern __shared__ char smem[];
    __shared__ int rowOff0[128], rowOff1[128];
    const uint32_t sb = smem_u32(smem);
    const int tid = threadIdx.x;
    const int wid = tid >> 5, lane = tid & 31;
    const int m0 = blockIdx.y * 128, n0 = blockIdx.x * 128;
    const int NC = K >> 6;

    if (MODE == 1 && tid < 128) {
        int m = m0 + tid;
        int b = m >> 14;
        int e = m & (Ee - 1);
        rowOff0[tid] = (b * Nn + idx0[e]) * Dd;
        rowOff1[tid] = (b * Nn + idx1[e]) * Dd;
        __syncthreads();
    } else if (MODE == 1) {
        __syncthreads();
    }

    // loader roles
    const int arow = tid >> 1;   // 0..127
    const int ah   = tid & 1;    // half of 128B row

    // warp tile roles: 2 (m) x 4 (n)
    const int wm = wid >> 2;     // 0..1 -> 64-row band
    const int wn = wid & 3;      // 0..3 -> 32-col band
    const int r15 = lane & 15;
    const int cs16 = (lane >> 4) * 16;
    int rowA[4], rowB[2];
#pragma unroll
    for (int mt = 0; mt < 4; mt++) rowA[mt] = (wm * 64 + mt * 16 + r15) << 7;
#pragma unroll
    for (int bt = 0; bt < 2; bt++) rowB[bt] = (wn * 32 + bt * 16 + r15) << 7;

    float acc[4][4][4];
#pragma unroll
    for (int i = 0; i < 4; i++)
#pragma unroll
        for (int j = 0; j < 4; j++)
#pragma unroll
            for (int q = 0; q < 4; q++) acc[i][j][q] = 0.f;

    float4 aSt[8];
    uint4  bStH[4], bStL[4];

    auto fetch = [&](int c) {
        const int kt = c * 64;
        const float* aptr;
        if (MODE == 0) {
            aptr = A0 + (size_t)(m0 + arow) * K + kt;
        } else if (MODE == 1) {
            int off = (kt < Dd) ? rowOff0[arow] : rowOff1[arow];
            aptr = A0 + off + ((kt < Dd) ? kt : kt - Dd);
        } else {
            aptr = (kt < MSGd) ? (A0 + (size_t)(m0 + arow) * MSGd + kt)
                               : (A1 + (size_t)(m0 + arow) * Dd + (kt - MSGd));
        }
#pragma unroll
        for (int j = 0; j < 8; j++)
            aSt[j] = *reinterpret_cast<const float4*>(aptr + (ah * 8 + j) * 4);
        const __nv_bfloat16* bh = WtHi + (size_t)(n0 + arow) * K + kt;
        const __nv_bfloat16* bl = WtLo + (size_t)(n0 + arow) * K + kt;
#pragma unroll
        for (int j = 0; j < 4; j++) {
            bStH[j] = *reinterpret_cast<const uint4*>(bh + (ah * 4 + j) * 8);
            bStL[j] = *reinterpret_cast<const uint4*>(bl + (ah * 4 + j) * 8);
        }
    };
    auto store = [&](int s) {
        char* stg = smem + s * STAGE_SZ;
#pragma unroll
        for (int j = 0; j < 8; j++) {
            float4 v = aSt[j];
            __nv_bfloat16 h0 = __float2bfloat16(v.x), h1 = __float2bfloat16(v.y);
            __nv_bfloat16 h2 = __float2bfloat16(v.z), h3 = __float2bfloat16(v.w);
            __nv_bfloat16 l0 = __float2bfloat16(v.x - __bfloat162float(h0));
            __nv_bfloat16 l1 = __float2bfloat16(v.y - __bfloat162float(h1));
            __nv_bfloat16 l2 = __float2bfloat16(v.z - __bfloat162float(h2));
            __nv_bfloat16 l3 = __float2bfloat16(v.w - __bfloat162float(h3));
            uint2 hv, lv;
            hv.x = (uint32_t)__bfloat16_as_ushort(h0) | ((uint32_t)__bfloat16_as_ushort(h1) << 16);
            hv.y = (uint32_t)__bfloat16_as_ushort(h2) | ((uint32_t)__bfloat16_as_ushort(h3) << 16);
            lv.x = (uint32_t)__bfloat16_as_ushort(l0) | ((uint32_t)__bfloat16_as_ushort(l1) << 16);
            lv.y = (uint32_t)__bfloat16_as_ushort(l2) | ((uint32_t)__bfloat16_as_ushort(l3) << 16);
            uint32_t off = sw128((arow << 7) + (ah * 8 + j) * 8);
            *reinterpret_cast<uint2*>(stg + off)         = hv;
            *reinterpret_cast<uint2*>(stg + 16384 + off) = lv;
        }
#pragma unroll
        for (int j = 0; j < 4; j++) {
            uint32_t off = sw128((arow << 7) + (ah * 4 + j) * 16);
            *reinterpret_cast<uint4*>(stg + 32768 + off) = bStH[j];
            *reinterpret_cast<uint4*>(stg + 49152 + off) = bStL[j];
        }
    };
    auto compute = [&](int s) {
        const uint32_t base = sb + s * STAGE_SZ;
#pragma unroll
        for (int ks = 0; ks < 4; ks++) {
            const int kb = ks * 32 + cs16;
            uint32_t ahF[4][4];
#pragma unroll
            for (int mt = 0; mt < 4; mt++) ldsm4(ahF[mt], base + sw128(rowA[mt] + kb));
            uint32_t bhF[2][4], blF[2][4];
#pragma unroll
            for (int bt = 0; bt < 2; bt++) {
                ldsm4(bhF[bt], base + 32768 + sw128(rowB[bt] + kb));
                ldsm4(blF[bt], base + 49152 + sw128(rowB[bt] + kb));
            }
#pragma unroll
            for (int mt = 0; mt < 4; mt++)
#pragma unroll
                for (int nt = 0; nt < 4; nt++) {
                    mma16816(acc[mt][nt], ahF[mt], bhF[nt >> 1][nt & 1], bhF[nt >> 1][(nt & 1) + 2]);
                    mma16816(acc[mt][nt], ahF[mt], blF[nt >> 1][nt & 1], blF[nt >> 1][(nt & 1) + 2]);
                }
            uint32_t alF[4][4];
#pragma unroll
            for (int mt = 0; mt < 4; mt++) ldsm4(alF[mt], base + 16384 + sw128(rowA[mt] + kb));
#pragma unroll
            for (int mt = 0; mt < 4; mt++)
#pragma unroll
                for (int nt = 0; nt < 4; nt++)
                    mma16816(acc[mt][nt], alF[mt], bhF[nt >> 1][nt & 1], bhF[nt >> 1][(nt & 1) + 2]);
        }
    };

    // ---- 2-stage software pipeline, 1 sync/iter ----
    fetch(0);
    store(0);
    if (NC > 1) fetch(1);
    __syncthreads();
    for (int c = 0; c < NC; c++) {
        if (c + 1 < NC) store((c + 1) & 1);
        if (c + 2 < NC) fetch(c + 2);
        compute(c & 1);
        __syncthreads();
    }

    // ---- epilogue ----
    const int g = lane >> 2, t4 = lane & 3;
#pragma unroll
    for (int mt = 0; mt < 4; mt++) {
        int mrow = m0 + wm * 64 + mt * 16 + g;
#pragma unroll
        for (int nt = 0; nt < 4; nt++) {
            int ncol = n0 + wn * 32 + nt * 8 + t4 * 2;
            float c0 = acc[mt][nt][0] + __ldg(bias + ncol);
            float c1 = acc[mt][nt][1] + __ldg(bias + ncol + 1);
            float c2 = acc[mt][nt][2] + __ldg(bias + ncol);
            float c3 = acc[mt][nt][3] + __ldg(bias + ncol + 1);
            if (RELU) {
                c0 = fmaxf(c0, 0.f); c1 = fmaxf(c1, 0.f);
                c2 = fmaxf(c2, 0.f); c3 = fmaxf(c3, 0.f);
            }
            if (ADDNS) {
                // C(=ns)[m*Dd + 2 + n] += v, only n < UPDd
                if (ncol < UPDd) {
                    C[(size_t)mrow * Dd + 2 + ncol] += c0;
                    C[(size_t)(mrow + 8) * Dd + 2 + ncol] += c2;
                }
                if (ncol + 1 < UPDd) {
                    C[(size_t)mrow * Dd + 2 + ncol + 1] += c1;
                    C[(size_t)(mrow + 8) * Dd + 2 + ncol + 1] += c3;
                }
            } else {
                *reinterpret_cast<float2*>(C + (size_t)mrow * ldc + ncol)       = make_float2(c0, c1);
                *reinterpret_cast<float2*>(C + (size_t)(mrow + 8) * ldc + ncol) = make_float2(c2, c3);
            }
        }
    }
}

// ---------------- extraction ----------------
__global__ void __launch_bounds__(256) extract_k(const float* __restrict__ attn,
                                                 const float* __restrict__ nsg,
                                                 float* __restrict__ out) {
    __shared__ float sa[512];
    int bp = blockIdx.x;
    int b = bp >> 6;
    const float* arow = attn + (size_t)bp * Nn;
    const float* nsb  = nsg + (size_t)b * Nn * Dd;
    int d = threadIdx.x;
    float acc = 0.f;
    for (int nb = 0; nb < Nn; nb += 512) {
        sa[d]       = arow[nb + d];
        sa[d + 256] = arow[nb + d + 256];
        __syncthreads();
#pragma unroll 8
        for (int n = 0; n < 512; n++)
            acc += sa[n] * nsb[(size_t)(nb + n) * Dd + d];
        __syncthreads();
    }
    out[(size_t)bp * Dd + d] = acc;
}

// ---------------- launch ----------------
extern "C" void kernel_launch(void* const* d_in, const int* in_sizes, int n_in,
                              void* d_out, int out_size) {
    const float* nodes = (const float*)d_in[0];
    const float* attn  = (const float*)d_in[1];
    const float* W_e1  = (const float*)d_in[2];
    const float* b_e1  = (const float*)d_in[3];
    const float* W_e2  = (const float*)d_in[4];
    const float* b_e2  = (const float*)d_in[5];
    const float* W_n1  = (const float*)d_in[6];
    const float* b_n1  = (const float*)d_in[7];
    const float* W_n2  = (const float*)d_in[8];
    const float* b_n2  = (const float*)d_in[9];
    const int*   srcI  = (const int*)d_in[10];
    const int*   snkI  = (const int*)d_in[11];
    // d_in[12] = msg_steps, fixed at 3 in the dataset

    float *p_ns, *p_he, *p_msgs, *p_inc, *p_h2, *p_b2p;
    __nv_bfloat16 *p_e1h, *p_e1l, *p_e2h, *p_e2l, *p_n1h, *p_n1l, *p_n2h, *p_n2l;
    cudaGetSymbolAddress((void**)&p_ns,   g_ns);
    cudaGetSymbolAddress((void**)&p_he,   g_he);
    cudaGetSymbolAddress((void**)&p_msgs, g_msgs);
    cudaGetSymbolAddress((void**)&p_inc,  g_inc);
    cudaGetSymbolAddress((void**)&p_h2,   g_h2);
    cudaGetSymbolAddress((void**)&p_b2p,  g_b2p);
    cudaGetSymbolAddress((void**)&p_e1h,  g_wte1h);
    cudaGetSymbolAddress((void**)&p_e1l,  g_wte1l);
    cudaGetSymbolAddress((void**)&p_e2h,  g_wte2h);
    cudaGetSymbolAddress((void**)&p_e2l,  g_wte2l);
    cudaGetSymbolAddress((void**)&p_n1h,  g_wtn1h);
    cudaGetSymbolAddress((void**)&p_n1l,  g_wtn1l);
    cudaGetSymbolAddress((void**)&p_n2h,  g_wtn2h);
    cudaGetSymbolAddress((void**)&p_n2l,  g_wtn2l);

    cudaFuncSetAttribute(gemm_mma<1, true,  false>, cudaFuncAttributeMaxDynamicSharedMemorySize, SMEM_BYTES);
    cudaFuncSetAttribute(gemm_mma<0, false, false>, cudaFuncAttributeMaxDynamicSharedMemorySize, SMEM_BYTES);
    cudaFuncSetAttribute(gemm_mma<2, true,  false>, cudaFuncAttributeMaxDynamicSharedMemorySize, SMEM_BYTES);
    cudaFuncSetAttribute(gemm_mma<0, false, true >, cudaFuncAttributeMaxDynamicSharedMemorySize, SMEM_BYTES);

    const int nsElems  = Bsz * Nn * Dd;
    const int incElems = Bsz * Nn * MSGd;

    // prep: working ns copy, bias pad, weight transpose+split
    copy4_k<<<nsElems / 4 / 256, 256>>>((float4*)p_ns, (const float4*)nodes, nsElems / 4);
    padb_k<<<1, 256>>>(b_n2);
    tsplit_k<<<(512 * 512 + 255) / 256, 256>>>(W_e1, p_e1h, p_e1l, 512, 512, 512);
    tsplit_k<<<(256 * 512 + 255) / 256, 256>>>(W_e2, p_e2h, p_e2l, 512, 256, 256);
    tsplit_k<<<(512 * 512 + 255) / 256, 256>>>(W_n1, p_n1h, p_n1l, 512, 512, 512);
    tsplit_k<<<(256 * 512 + 255) / 256, 256>>>(W_n2, p_n2h, p_n2l, 512, 256, 254);

    const int ME = Bsz * Ee;   // 131072 edge rows
    const int MN = Bsz * Nn;   // 32768 node rows

    for (int s = 0; s < STEPS; s++) {
        // edge MLP L1: gather concat[src,snk] (K=512) @ W_e1 -> relu -> he
        gemm_mma<1, true, false><<<dim3(Hh / 128, ME / 128), 256, SMEM_BYTES>>>(
            p_ns, nullptr, srcI, snkI, p_e1h, p_e1l, b_e1, p_he, 2 * Dd, Hh);
        // edge MLP L2: he (K=512) @ W_e2 -> msgs
        gemm_mma<0, false, false><<<dim3(MSGd / 128, ME / 128), 256, SMEM_BYTES>>>(
            p_he, nullptr, nullptr, nullptr, p_e2h, p_e2l, b_e2, p_msgs, Hh, MSGd);
        // zero + scatter-add incoming
        zero4_k<<<incElems / 4 / 256, 256>>>((float4*)p_inc, incElems / 4);
        scatter_k<<<ME, MSGd>>>(p_msgs, snkI, p_inc);
        // node MLP L1: concat[incoming, ns] (K=512) @ W_n1 -> relu -> h2
        gemm_mma<2, true, false><<<dim3(Hh / 128, MN / 128), 256, SMEM_BYTES>>>(
            p_inc, p_ns, nullptr, nullptr, p_n1h, p_n1l, b_n1, p_h2, MSGd + Dd, Hh);
        // node MLP L2 + residual into ns[:, :, 2:256]
        gemm_mma<0, false, true><<<dim3(256 / 128, MN / 128), 256, SMEM_BYTES>>>(
            p_h2, nullptr, nullptr, nullptr, p_n2h, p_n2l, p_b2p, p_ns, Hh, Dd);
    }

    // extraction: (B,P,N) x (B,N,D) -> (B,P,D)
    extract_k<<<Bsz * Pp, 256>>>(attn, p_ns, (float*)d_out);
}

// round 6
// speedup vs baseline: 2.2807x; 1.2953x over previous
#include <cuda_runtime.h>
#include <cuda_bf16.h>
#include <cstddef>
#include <cstdint>

// Problem constants (fixed by setup_inputs)
#define Bsz  8
#define Nn   4096
#define Ee   16384
#define Pp   64
#define Dd   256
#define Hh   512
#define MSGd 256
#define UPDd 254
#define STEPS 3

// ---------------- scratch (allocation-free: __device__ globals) ----------------
__device__ float g_ns  [(size_t)Bsz*Nn*Dd];    // working node states
__device__ float g_he  [(size_t)Bsz*Ee*Hh];    // edge hidden
__device__ float g_inc [(size_t)Bsz*Nn*MSGd];  // incoming
__device__ float g_h2  [(size_t)Bsz*Nn*Hh];    // node hidden
__device__ float g_b2p [256];                  // b_n2 padded
// transposed + hi/lo-split weights (bf16), layout Wt[N][K] K-major
__device__ __nv_bfloat16 g_wte1h[512*512], g_wte1l[512*512];
__device__ __nv_bfloat16 g_wte2h[256*512], g_wte2l[256*512];
__device__ __nv_bfloat16 g_wtn1h[512*512], g_wtn1l[512*512];
__device__ __nv_bfloat16 g_wtn2h[256*512], g_wtn2l[256*512];

// ---------------- PTX helpers (family-portable: ldmatrix / mma.sync / cp.async) ----------------
__device__ __forceinline__ uint32_t smem_u32(const void* p) {
    uint32_t a;
    asm("{ .reg .u64 t; cvta.to.shared.u64 t, %1; cvt.u32.u64 %0, t; }" : "=r"(a) : "l"(p));
    return a;
}
__device__ __forceinline__ void ldsm4(uint32_t* r, uint32_t addr) {
    asm volatile("ldmatrix.sync.aligned.m8n8.x4.shared.b16 {%0,%1,%2,%3}, [%4];"
                 : "=r"(r[0]), "=r"(r[1]), "=r"(r[2]), "=r"(r[3]) : "r"(addr));
}
__device__ __forceinline__ void mma16816(float* c, const uint32_t* a, uint32_t b0, uint32_t b1) {
    asm volatile(
        "mma.sync.aligned.m16n8k16.row.col.f32.bf16.bf16.f32 "
        "{%0,%1,%2,%3}, {%4,%5,%6,%7}, {%8,%9}, {%0,%1,%2,%3};"
        : "+f"(c[0]), "+f"(c[1]), "+f"(c[2]), "+f"(c[3])
        : "r"(a[0]), "r"(a[1]), "r"(a[2]), "r"(a[3]), "r"(b0), "r"(b1));
}
__device__ __forceinline__ void cp16(uint32_t dst, const void* src) {
    asm volatile("cp.async.cg.shared.global [%0], [%1], 16;" :: "r"(dst), "l"(src));
}
__device__ __forceinline__ void cp_commit() {
    asm volatile("cp.async.commit_group;" ::: "memory");
}
__device__ __forceinline__ void cp_wait0() {
    asm volatile("cp.async.wait_group 0;" ::: "memory");
}
__device__ __forceinline__ uint32_t sw128(uint32_t off) { return off ^ ((off >> 3) & 0x70); }

// ---------------- small utility kernels ----------------
__global__ void copy4_k(float4* __restrict__ dst, const float4* __restrict__ src, int n4) {
    int i = blockIdx.x * blockDim.x + threadIdx.x;
    if (i < n4) dst[i] = src[i];
}
__global__ void zero4_k(float4* __restrict__ dst, int n4) {
    int i = blockIdx.x * blockDim.x + threadIdx.x;
    if (i < n4) dst[i] = make_float4(0.f, 0.f, 0.f, 0.f);
}
__global__ void padb_k(const float* __restrict__ b) {
    int i = threadIdx.x;
    g_b2p[i] = (i < UPDd) ? b[i] : 0.f;
}
// one kernel: transpose + hi/lo split all four weight matrices
__global__ void tsplit_all(const float* __restrict__ We1, const float* __restrict__ We2,
                           const float* __restrict__ Wn1, const float* __restrict__ Wn2) {
    int i = blockIdx.x * 256 + threadIdx.x;   // 0 .. 786431
    const float* W; __nv_bfloat16 *Hi, *Lo;
    int base, srcN;
    if (i < 262144)      { W = We1; Hi = g_wte1h; Lo = g_wte1l; base = 0;      srcN = 512; }
    else if (i < 393216) { W = We2; Hi = g_wte2h; Lo = g_wte2l; base = 262144; srcN = 256; }
    else if (i < 655360) { W = Wn1; Hi = g_wtn1h; Lo = g_wtn1l; base = 393216; srcN = 512; }
    else                 { W = Wn2; Hi = g_wtn2h; Lo = g_wtn2l; base = 655360; srcN = 254; }
    int local = i - base;
    int n = local >> 9, k = local & 511;      // K = 512 everywhere
    float v = (n < srcN) ? W[(size_t)k * srcN + n] : 0.f;
    __nv_bfloat16 h = __float2bfloat16(v);
    Hi[local] = h;
    Lo[local] = __float2bfloat16(v - __bfloat162float(h));
}

// ---------------- HMMA GEMM: CTA 128x256, warp tile 64x64, BK=64, 3-pass hi/lo ----------------
// MODE 0: A0[m][k] row-major, row stride = K
// MODE 1: gather concat: k<256 -> ns[rowOff0[m]+k], else ns[rowOff1[m]+k-256]
// MODE 2: concat: k<256 -> A0[m*256+k] (incoming), else A1[m*256+(k-256)] (ns)
// EPI  0: store   1: relu store   2: +=ns residual (cols 2..255)   3: atomicAdd into inc[sink]
// Dyn smem per stage (96 KB): AHI 16K | ALO 16K | BHI 32K | BLO 32K. 2 stages.
#define STAGE_SZ 98304
#define SMEM_BYTES (2 * STAGE_SZ)
#define OFF_AL 16384
#define OFF_BH 32768
#define OFF_BL 65536

template <int MODE, int EPI>
__global__ void __launch_bounds__(256, 1)
gemm_mma(const float* __restrict__ A0, const float* __restrict__ A1,
         const int* __restrict__ idx0, const int* __restrict__ idx1,
         const __nv_bfloat16* __restrict__ WtHi, const __nv_bfloat16* __restrict__ WtLo,
         const float* __restrict__ bias, float* __restrict__ C,
         int K, int ldc)
{
    extern __shared__ char smem[];
    __shared__ int rowOff0[128], rowOff1[128];
    __shared__ int sOff[128];
    const uint32_t sb = smem_u32(smem);
    const int tid = threadIdx.x;
    const int wid = tid >> 5, lane = tid & 31;
    const int m0 = blockIdx.y * 128, n0 = blockIdx.x * 256;
    const int NC = K >> 6;

    if (MODE == 1 && tid < 128) {
        int m = m0 + tid;
        int b = m >> 14;
        int e = m & (Ee - 1);
        rowOff0[tid] = (b * Nn + idx0[e]) * Dd;
        rowOff1[tid] = (b * Nn + idx1[e]) * Dd;
    }
    if (EPI == 3 && tid < 128) {
        int m = m0 + tid;
        int b = m >> 14;
        int e = m & (Ee - 1);
        sOff[tid] = (b * Nn + idx1[e]) * MSGd;
    }
    __syncthreads();

    // loader roles (A): 2 threads per row
    const int arow = tid >> 1;   // 0..127
    const int ah   = tid & 1;
    // loader roles (B cp.async): 8 threads per row group
    const int bu = tid & 7;          // 16B unit within 128B row
    const int br0 = tid >> 3;        // 0..31

    // warp tile roles: 2 (m) x 4 (n), 64x64 each
    const int wm = wid >> 2;
    const int wn = wid & 3;
    const int r15 = lane & 15;
    const int cs16 = (lane >> 4) * 16;
    int rowA[4], rowB[4];
#pragma unroll
    for (int mt = 0; mt < 4; mt++) rowA[mt] = (wm * 64 + mt * 16 + r15) << 7;
#pragma unroll
    for (int bt = 0; bt < 4; bt++) rowB[bt] = (wn * 64 + bt * 16 + r15) << 7;

    float acc[4][8][4];
#pragma unroll
    for (int i = 0; i < 4; i++)
#pragma unroll
        for (int j = 0; j < 8; j++)
#pragma unroll
            for (int q = 0; q < 4; q++) acc[i][j][q] = 0.f;

    float4 aSt[8];

    auto fetchA = [&](int c) {
        const int kt = c * 64;
        const float* aptr;
        if (MODE == 0) {
            aptr = A0 + (size_t)(m0 + arow) * K + kt;
        } else if (MODE == 1) {
            int off = (kt < Dd) ? rowOff0[arow] : rowOff1[arow];
            aptr = A0 + off + ((kt < Dd) ? kt : kt - Dd);
        } else {
            aptr = (kt < MSGd) ? (A0 + (size_t)(m0 + arow) * MSGd + kt)
                               : (A1 + (size_t)(m0 + arow) * Dd + (kt - MSGd));
        }
#pragma unroll
        for (int j = 0; j < 8; j++)
            aSt[j] = *reinterpret_cast<const float4*>(aptr + (ah * 8 + j) * 4);
    };
    auto storeA = [&](int s) {
        char* stg = smem + s * STAGE_SZ;
#pragma unroll
        for (int j = 0; j < 8; j++) {
            float4 v = aSt[j];
            __nv_bfloat16 h0 = __float2bfloat16(v.x), h1 = __float2bfloat16(v.y);
            __nv_bfloat16 h2 = __float2bfloat16(v.z), h3 = __float2bfloat16(v.w);
            __nv_bfloat16 l0 = __float2bfloat16(v.x - __bfloat162float(h0));
            __nv_bfloat16 l1 = __float2bfloat16(v.y - __bfloat162float(h1));
            __nv_bfloat16 l2 = __float2bfloat16(v.z - __bfloat162float(h2));
            __nv_bfloat16 l3 = __float2bfloat16(v.w - __bfloat162float(h3));
            uint2 hv, lv;
            hv.x = (uint32_t)__bfloat16_as_ushort(h0) | ((uint32_t)__bfloat16_as_ushort(h1) << 16);
            hv.y = (uint32_t)__bfloat16_as_ushort(h2) | ((uint32_t)__bfloat16_as_ushort(h3) << 16);
            lv.x = (uint32_t)__bfloat16_as_ushort(l0) | ((uint32_t)__bfloat16_as_ushort(l1) << 16);
            lv.y = (uint32_t)__bfloat16_as_ushort(l2) | ((uint32_t)__bfloat16_as_ushort(l3) << 16);
            uint32_t off = sw128((arow << 7) + (ah * 8 + j) * 8);
            *reinterpret_cast<uint2*>(stg + off)          = hv;
            *reinterpret_cast<uint2*>(stg + OFF_AL + off) = lv;
        }
    };
    auto cpB = [&](int c) {
        const int kt = c * 64;
        const uint32_t stg = sb + (c & 1) * STAGE_SZ;
#pragma unroll
        for (int i = 0; i < 8; i++) {
            int r = br0 + 32 * i;
            uint32_t off = sw128((r << 7) + bu * 16);
            cp16(stg + OFF_BH + off, WtHi + (size_t)(n0 + r) * K + kt + bu * 8);
            cp16(stg + OFF_BL + off, WtLo + (size_t)(n0 + r) * K + kt + bu * 8);
        }
    };
    auto compute = [&](int s) {
        const uint32_t base = sb + s * STAGE_SZ;
#pragma unroll
        for (int ks = 0; ks < 4; ks++) {
            const int kb = ks * 32 + cs16;
            uint32_t ahF[4][4];
#pragma unroll
            for (int mt = 0; mt < 4; mt++) ldsm4(ahF[mt], base + sw128(rowA[mt] + kb));
            uint32_t bhF[4][4], blF[4][4];
#pragma unroll
            for (int bt = 0; bt < 4; bt++) {
                ldsm4(bhF[bt], base + OFF_BH + sw128(rowB[bt] + kb));
                ldsm4(blF[bt], base + OFF_BL + sw128(rowB[bt] + kb));
            }
#pragma unroll
            for (int mt = 0; mt < 4; mt++)
#pragma unroll
                for (int nt = 0; nt < 8; nt++) {
                    mma16816(acc[mt][nt], ahF[mt], bhF[nt >> 1][nt & 1], bhF[nt >> 1][(nt & 1) + 2]);
                    mma16816(acc[mt][nt], ahF[mt], blF[nt >> 1][nt & 1], blF[nt >> 1][(nt & 1) + 2]);
                }
            uint32_t alF[4][4];
#pragma unroll
            for (int mt = 0; mt < 4; mt++) ldsm4(alF[mt], base + OFF_AL + sw128(rowA[mt] + kb));
#pragma unroll
            for (int mt = 0; mt < 4; mt++)
#pragma unroll
                for (int nt = 0; nt < 8; nt++)
                    mma16816(acc[mt][nt], alF[mt], bhF[nt >> 1][nt & 1], bhF[nt >> 1][(nt & 1) + 2]);
        }
    };

    // ---- 2-stage pipeline, 1 sync/iter ----
    fetchA(0);
    storeA(0);
    cpB(0); cp_commit();
    if (NC > 1) fetchA(1);
    cp_wait0();
    __syncthreads();
    for (int c = 0; c < NC; c++) {
        if (c + 1 < NC) { storeA((c + 1) & 1); cpB(c + 1); cp_commit(); }
        if (c + 2 < NC) fetchA(c + 2);
        compute(c & 1);
        if (c + 1 < NC) cp_wait0();
        __syncthreads();
    }

    // ---- epilogue ----
    const int g = lane >> 2, t4 = lane & 3;
#pragma unroll
    for (int mt = 0; mt < 4; mt++) {
        int lr = wm * 64 + mt * 16 + g;
        int mrow = m0 + lr;
#pragma unroll
        for (int nt = 0; nt < 8; nt++) {
            int ncol = n0 + wn * 64 + nt * 8 + t4 * 2;
            float c0 = acc[mt][nt][0] + __ldg(bias + ncol);
            float c1 = acc[mt][nt][1] + __ldg(bias + ncol + 1);
            float c2 = acc[mt][nt][2] + __ldg(bias + ncol);
            float c3 = acc[mt][nt][3] + __ldg(bias + ncol + 1);
            if (EPI == 1) {
                c0 = fmaxf(c0, 0.f); c1 = fmaxf(c1, 0.f);
                c2 = fmaxf(c2, 0.f); c3 = fmaxf(c3, 0.f);
            }
            if (EPI == 0 || EPI == 1) {
                *reinterpret_cast<float2*>(C + (size_t)mrow * ldc + ncol)       = make_float2(c0, c1);
                *reinterpret_cast<float2*>(C + (size_t)(mrow + 8) * ldc + ncol) = make_float2(c2, c3);
            } else if (EPI == 2) {
                // C(=ns)[m*Dd + 2 + n] += v, only n < UPDd
                if (ncol < UPDd) {
                    C[(size_t)mrow * Dd + 2 + ncol]       += c0;
                    C[(size_t)(mrow + 8) * Dd + 2 + ncol] += c2;
                }
                if (ncol + 1 < UPDd) {
                    C[(size_t)mrow * Dd + 2 + ncol + 1]       += c1;
                    C[(size_t)(mrow + 8) * Dd + 2 + ncol + 1] += c3;
                }
            } else {
                // EPI 3: atomic scatter into inc[sink]
                atomicAdd(C + sOff[lr] + ncol,     c0);
                atomicAdd(C + sOff[lr] + ncol + 1, c1);
                atomicAdd(C + sOff[lr + 8] + ncol,     c2);
                atomicAdd(C + sOff[lr + 8] + ncol + 1, c3);
            }
        }
    }
}

// ---------------- extraction ----------------
__global__ void __launch_bounds__(256) extract_k(const float* __restrict__ attn,
                                                 const float* __restrict__ nsg,
                                                 float* __restrict__ out) {
    __shared__ float sa[512];
    int bp = blockIdx.x;
    int b = bp >> 6;
    const float* arow = attn + (size_t)bp * Nn;
    const float* nsb  = nsg + (size_t)b * Nn * Dd;
    int d = threadIdx.x;
    float acc = 0.f;
    for (int nb = 0; nb < Nn; nb += 512) {
        sa[d]       = arow[nb + d];
        sa[d + 256] = arow[nb + d + 256];
        __syncthreads();
#pragma unroll 8
        for (int n = 0; n < 512; n++)
            acc += sa[n] * nsb[(size_t)(nb + n) * Dd + d];
        __syncthreads();
    }
    out[(size_t)bp * Dd + d] = acc;
}

// ---------------- launch ----------------
extern "C" void kernel_launch(void* const* d_in, const int* in_sizes, int n_in,
                              void* d_out, int out_size) {
    const float* nodes = (const float*)d_in[0];
    const float* attn  = (const float*)d_in[1];
    const float* W_e1  = (const float*)d_in[2];
    const float* b_e1  = (const float*)d_in[3];
    const float* W_e2  = (const float*)d_in[4];
    const float* b_e2  = (const float*)d_in[5];
    const float* W_n1  = (const float*)d_in[6];
    const float* b_n1  = (const float*)d_in[7];
    const float* W_n2  = (const float*)d_in[8];
    const float* b_n2  = (const float*)d_in[9];
    const int*   srcI  = (const int*)d_in[10];
    const int*   snkI  = (const int*)d_in[11];
    // d_in[12] = msg_steps, fixed at 3 in the dataset

    float *p_ns, *p_he, *p_inc, *p_h2, *p_b2p;
    __nv_bfloat16 *p_e1h, *p_e1l, *p_e2h, *p_e2l, *p_n1h, *p_n1l, *p_n2h, *p_n2l;
    cudaGetSymbolAddress((void**)&p_ns,   g_ns);
    cudaGetSymbolAddress((void**)&p_he,   g_he);
    cudaGetSymbolAddress((void**)&p_inc,  g_inc);
    cudaGetSymbolAddress((void**)&p_h2,   g_h2);
    cudaGetSymbolAddress((void**)&p_b2p,  g_b2p);
    cudaGetSymbolAddress((void**)&p_e1h,  g_wte1h);
    cudaGetSymbolAddress((void**)&p_e1l,  g_wte1l);
    cudaGetSymbolAddress((void**)&p_e2h,  g_wte2h);
    cudaGetSymbolAddress((void**)&p_e2l,  g_wte2l);
    cudaGetSymbolAddress((void**)&p_n1h,  g_wtn1h);
    cudaGetSymbolAddress((void**)&p_n1l,  g_wtn1l);
    cudaGetSymbolAddress((void**)&p_n2h,  g_wtn2h);
    cudaGetSymbolAddress((void**)&p_n2l,  g_wtn2l);

    cudaFuncSetAttribute(gemm_mma<1, 1>, cudaFuncAttributeMaxDynamicSharedMemorySize, SMEM_BYTES);
    cudaFuncSetAttribute(gemm_mma<0, 3>, cudaFuncAttributeMaxDynamicSharedMemorySize, SMEM_BYTES);
    cudaFuncSetAttribute(gemm_mma<2, 1>, cudaFuncAttributeMaxDynamicSharedMemorySize, SMEM_BYTES);
    cudaFuncSetAttribute(gemm_mma<0, 2>, cudaFuncAttributeMaxDynamicSharedMemorySize, SMEM_BYTES);

    const int nsElems  = Bsz * Nn * Dd;
    const int incElems = Bsz * Nn * MSGd;

    // prep (3 launches so ncu -s 5 lands on a GEMM)
    copy4_k<<<nsElems / 4 / 256, 256>>>((float4*)p_ns, (const float4*)nodes, nsElems / 4);
    padb_k<<<1, 256>>>(b_n2);
    tsplit_all<<<3072, 256>>>(W_e1, W_e2, W_n1, W_n2);

    const int ME = Bsz * Ee;   // 131072 edge rows
    const int MN = Bsz * Nn;   // 32768 node rows

    for (int s = 0; s < STEPS; s++) {
        // zero incoming (consumed by fused scatter in edge L2 epilogue)
        zero4_k<<<incElems / 4 / 256, 256>>>((float4*)p_inc, incElems / 4);
        // edge MLP L1: gather concat[src,snk] (K=512) @ W_e1 -> relu -> he
        gemm_mma<1, 1><<<dim3(Hh / 256, ME / 128), 256, SMEM_BYTES>>>(
            p_ns, nullptr, srcI, snkI, p_e1h, p_e1l, b_e1, p_he, 2 * Dd, Hh);
        // edge MLP L2: he (K=512) @ W_e2 + b -> atomicAdd into inc[sink]
        gemm_mma<0, 3><<<dim3(MSGd / 256, ME / 128), 256, SMEM_BYTES>>>(
            p_he, nullptr, nullptr, snkI, p_e2h, p_e2l, b_e2, p_inc, Hh, MSGd);
        // node MLP L1: concat[incoming, ns] (K=512) @ W_n1 -> relu -> h2
        gemm_mma<2, 1><<<dim3(Hh / 256, MN / 128), 256, SMEM_BYTES>>>(
            p_inc, p_ns, nullptr, nullptr, p_n1h, p_n1l, b_n1, p_h2, MSGd + Dd, Hh);
        // node MLP L2 + residual into ns[:, :, 2:256]
        gemm_mma<0, 2><<<dim3(256 / 256, MN / 128), 256, SMEM_BYTES>>>(
            p_h2, nullptr, nullptr, nullptr, p_n2h, p_n2l, p_b2p, p_ns, Hh, Dd);
    }

    // extraction: (B,P,N) x (B,N,D) -> (B,P,D)
    extract_k<<<Bsz * Pp, 256>>>(attn, p_ns, (float*)d_out);
}